// round 3
// baseline (speedup 1.0000x reference)
#include <cuda_runtime.h>

#define NN 100000
#define NE 1600000

// ---------------- scratch (device globals; no allocation) ----------------
__device__ __align__(16) float g_h[NN * 128];      // projected features
__device__ __align__(16) float g_asrc[NN * 4];     // per-node src attention logits
__device__ __align__(16) float g_adst[NN * 4];     // per-node dst attention logits
__device__ __align__(16) float g_w[NE * 4];        // exp(leaky(e)) per edge/head
__device__ __align__(16) float g_denom[NN * 4];    // softmax denominators
__device__ int g_src[NE];
__device__ int g_dst[NE];
__device__ int g_is64;
__device__ float g_sum[128];
__device__ float g_sq[128];
__device__ __align__(16) float g_scale[128];
__device__ __align__(16) float g_shift[128];

__device__ __forceinline__ void red_add_v4(float* p, float4 v) {
    asm volatile("red.global.add.v4.f32 [%0], {%1,%2,%3,%4};"
                 :: "l"(p), "f"(v.x), "f"(v.y), "f"(v.z), "f"(v.w) : "memory");
}
__device__ __forceinline__ float lrelu(float v) { return v > 0.f ? v : 0.2f * v; }

// ---------------- K-detect: int64 vs int32 edge_index ----------------
// int64 node indices are < 100000, so every 8-byte word is < NN.
// int32 data reinterpreted as u64 packs two indices -> almost surely >= 2^32.
__global__ void k_detect(const unsigned long long* __restrict__ e) {
    if (threadIdx.x == 0 && blockIdx.x == 0) {
        int is64 = 1;
        for (int i = 0; i < 64; i++)
            if (e[i] >= (unsigned long long)NN) { is64 = 0; break; }
        g_is64 = is64;
    }
}

// ---------------- K-convert: materialize int32 src/dst (clamped) ----------------
__global__ void k_convert(const void* __restrict__ ep) {
    int i = blockIdx.x * blockDim.x + threadIdx.x;
    if (i >= NE) return;
    long long s, d;
    if (g_is64) {
        const long long* e = (const long long*)ep;
        s = e[i]; d = e[NE + i];
    } else {
        const int* e = (const int*)ep;
        s = e[i]; d = e[NE + i];
    }
    if (s < 0) s = 0; if (s > NN - 1) s = NN - 1;
    if (d < 0) d = 0; if (d > NN - 1) d = NN - 1;
    g_src[i] = (int)s;
    g_dst[i] = (int)d;
}

// ---------------- K0: zero accumulators ----------------
__global__ void k_init(float* __restrict__ out) {
    int tid = blockIdx.x * blockDim.x + threadIdx.x;
    int stride = gridDim.x * blockDim.x;
    float4 z = make_float4(0.f, 0.f, 0.f, 0.f);
    float4* o4 = (float4*)out;
    for (int j = tid; j < NN * 32; j += stride) o4[j] = z;
    float4* d4 = (float4*)g_denom;
    for (int j = tid; j < NN; j += stride) d4[j] = z;
    if (tid < 128) { g_sum[tid] = 0.f; g_sq[tid] = 0.f; }
}

// ---------------- K1: h = x @ W  (fp32 register-tiled GEMM) ----------------
// Block: 256 threads, 64 rows x 128 cols tile. Thread t: tx=t&31, ty=t>>5.
// Thread computes rows {ty+8i} (8) x cols {tx+32m} (4)  -> conflict-free LDS.
__global__ __launch_bounds__(256) void k_gemm(const float* __restrict__ x,
                                              const float* __restrict__ W) {
    __shared__ float Wsh[32 * 128];   // [kk][c]
    __shared__ float xs[32 * 65];     // [kk][row] (padded)
    int t = threadIdx.x;
    int tx = t & 31, ty = t >> 5;
    int row0 = blockIdx.x * 64;

    float acc[8][4];
#pragma unroll
    for (int i = 0; i < 8; i++)
#pragma unroll
        for (int m = 0; m < 4; m++) acc[i][m] = 0.f;

    for (int c = 0; c < 4; c++) {
        int k0 = c * 32;
        // load W chunk [32][128]
        {
            int c4 = t & 31, krb = t >> 5;
            const float4* W4 = (const float4*)W;
#pragma unroll
            for (int j = 0; j < 4; j++) {
                int kr = krb + j * 8;
                ((float4*)Wsh)[kr * 32 + c4] = W4[(k0 + kr) * 32 + c4];
            }
        }
        // load x chunk transposed into xs[kk][row]
        {
            int rowL = t >> 2, kq = t & 3;
            int gr = row0 + rowL; if (gr > NN - 1) gr = NN - 1;
            const float4* x4 = (const float4*)x;
            float4 v0 = x4[gr * 32 + c * 8 + kq];
            float4 v1 = x4[gr * 32 + c * 8 + kq + 4];
            int kb = kq * 4;
            xs[(kb + 0) * 65 + rowL] = v0.x;
            xs[(kb + 1) * 65 + rowL] = v0.y;
            xs[(kb + 2) * 65 + rowL] = v0.z;
            xs[(kb + 3) * 65 + rowL] = v0.w;
            xs[(kb + 16) * 65 + rowL] = v1.x;
            xs[(kb + 17) * 65 + rowL] = v1.y;
            xs[(kb + 18) * 65 + rowL] = v1.z;
            xs[(kb + 19) * 65 + rowL] = v1.w;
        }
        __syncthreads();
#pragma unroll
        for (int kk = 0; kk < 32; kk++) {
            float wv0 = Wsh[kk * 128 + tx];
            float wv1 = Wsh[kk * 128 + tx + 32];
            float wv2 = Wsh[kk * 128 + tx + 64];
            float wv3 = Wsh[kk * 128 + tx + 96];
#pragma unroll
            for (int i = 0; i < 8; i++) {
                float xv = xs[kk * 65 + ty + 8 * i];
                acc[i][0] += xv * wv0;
                acc[i][1] += xv * wv1;
                acc[i][2] += xv * wv2;
                acc[i][3] += xv * wv3;
            }
        }
        __syncthreads();
    }
#pragma unroll
    for (int i = 0; i < 8; i++) {
        int g = row0 + ty + 8 * i;
        if (g < NN) {
#pragma unroll
            for (int m = 0; m < 4; m++)
                g_h[g * 128 + tx + 32 * m] = acc[i][m];
        }
    }
}

// ---------------- K1b: per-node attention logits (warp per node) ----------------
// att_src/att_dst are (HEADS=4, HEAD_DIM=32) row-major = 128 floats.
// column c_global = m*32+lane -> head = m, within-head dim = lane.
__global__ void k_att(const float* __restrict__ att_src, const float* __restrict__ att_dst) {
    int gw = (blockIdx.x * blockDim.x + threadIdx.x) >> 5;
    if (gw >= NN) return;
    int lane = threadIdx.x & 31;
    float s[4], d[4];
#pragma unroll
    for (int m = 0; m < 4; m++) {
        float hv = g_h[gw * 128 + m * 32 + lane];
        s[m] = hv * __ldg(&att_src[m * 32 + lane]);
        d[m] = hv * __ldg(&att_dst[m * 32 + lane]);
    }
    for (int off = 16; off > 0; off >>= 1) {
#pragma unroll
        for (int m = 0; m < 4; m++) {
            s[m] += __shfl_xor_sync(0xffffffffu, s[m], off);
            d[m] += __shfl_xor_sync(0xffffffffu, d[m], off);
        }
    }
    if (lane == 0) {
        *(float4*)&g_asrc[gw * 4] = make_float4(s[0], s[1], s[2], s[3]);
        *(float4*)&g_adst[gw * 4] = make_float4(d[0], d[1], d[2], d[3]);
    }
}

// ---------------- K2: edge weights + softmax denominators ----------------
// No max-subtraction needed: softmax is shift-invariant, |e| small -> no overflow.
__global__ void k_edge_w() {
    int e = blockIdx.x * blockDim.x + threadIdx.x;
    if (e >= NE) return;
    int src = g_src[e];
    int dst = g_dst[e];
    float4 s = *(const float4*)&g_asrc[src * 4];
    float4 d = *(const float4*)&g_adst[dst * 4];
    float4 w;
    w.x = __expf(lrelu(s.x + d.x));
    w.y = __expf(lrelu(s.y + d.y));
    w.z = __expf(lrelu(s.z + d.z));
    w.w = __expf(lrelu(s.w + d.w));
    *(float4*)&g_w[e * 4] = w;
    red_add_v4(&g_denom[dst * 4], w);
}

// ---------------- K3: alpha-weighted scatter-add aggregation (warp per edge) ----------------
__global__ void k_aggregate(float* __restrict__ out) {
    int gw = (blockIdx.x * blockDim.x + threadIdx.x) >> 5;
    if (gw >= NE) return;
    int lane = threadIdx.x & 31;
    int src = g_src[gw];
    int dst = g_dst[gw];
    int head = lane >> 3;
    float wv = __ldg(&g_w[gw * 4 + head]);
    float dv = __ldg(&g_denom[dst * 4 + head]);
    float alpha = wv / (dv + 1e-16f);
    float4 hv = *(const float4*)&g_h[src * 128 + lane * 4];
    float4 msg = make_float4(alpha * hv.x, alpha * hv.y, alpha * hv.z, alpha * hv.w);
    red_add_v4(&out[dst * 128 + lane * 4], msg);
}

// ---------------- K4: BN batch statistics ----------------
__global__ void k_bnstats(const float* __restrict__ out) {
    int c = threadIdx.x & 127;
    int rofs = threadIdx.x >> 7;   // 256 threads -> 2 rows per iter
    float s = 0.f, q = 0.f;
    for (int r = blockIdx.x * 2 + rofs; r < NN; r += gridDim.x * 2) {
        float v = out[r * 128 + c];
        s += v; q += v * v;
    }
    atomicAdd(&g_sum[c], s);
    atomicAdd(&g_sq[c], q);
}

// ---------------- K4b: finalize per-channel scale/shift ----------------
// Note: +bias before BN cancels exactly (BN subtracts the batch mean), so it is skipped.
__global__ void k_bnfinal(const float* __restrict__ gamma, const float* __restrict__ beta) {
    int c = threadIdx.x;
    float inv_n = 1.f / (float)NN;
    float mu = g_sum[c] * inv_n;
    float var = g_sq[c] * inv_n - mu * mu;
    float inv = rsqrtf(var + 1e-5f);
    float sc = gamma[c] * inv;
    g_scale[c] = sc;
    g_shift[c] = beta[c] - mu * sc;
}

// ---------------- K5: normalize + LeakyReLU (in place on d_out) ----------------
__global__ void k_norm(float* __restrict__ out) {
    int tid = blockIdx.x * blockDim.x + threadIdx.x;
    int stride = gridDim.x * blockDim.x;
    float4* o4 = (float4*)out;
    const float4* sc4 = (const float4*)g_scale;
    const float4* sh4 = (const float4*)g_shift;
    for (int j = tid; j < NN * 32; j += stride) {
        float4 v = o4[j];
        float4 sc = __ldg(&sc4[j & 31]);
        float4 sh = __ldg(&sh4[j & 31]);
        v.x = lrelu(v.x * sc.x + sh.x);
        v.y = lrelu(v.y * sc.y + sh.y);
        v.z = lrelu(v.z * sc.z + sh.z);
        v.w = lrelu(v.w * sc.w + sh.w);
        o4[j] = v;
    }
}

// ---------------- launch ----------------
extern "C" void kernel_launch(void* const* d_in, const int* in_sizes, int n_in,
                              void* d_out, int out_size) {
    // Unique-size buffers bound by size; the five 128-element buffers bound by
    // order of appearance (dict order: att_src, att_dst, bias, gamma, beta).
    const float* x = 0; const void* ei = 0; const float* W = 0;
    const float* att_src = 0; const float* att_dst = 0;
    const float* gamma = 0; const float* beta = 0;
    int n128 = 0;
    for (int i = 0; i < n_in; i++) {
        int sz = in_sizes[i];
        if (sz == NN * 128)        { x = (const float*)d_in[i]; }
        else if (sz == 2 * NE)     { ei = d_in[i]; }
        else if (sz == 128 * 128)  { W = (const float*)d_in[i]; }
        else if (sz == 128) {
            if (n128 == 0)      att_src = (const float*)d_in[i];
            else if (n128 == 1) att_dst = (const float*)d_in[i];
            // n128 == 2 -> bias: cancels exactly under batch-stat BN, unused
            else if (n128 == 3) gamma = (const float*)d_in[i];
            else if (n128 == 4) beta  = (const float*)d_in[i];
            n128++;
        }
    }
    float* out = (float*)d_out;
    if (!x || !ei || !W || !att_src || !att_dst || !gamma || !beta) return;

    k_detect<<<1, 32>>>((const unsigned long long*)ei);
    k_convert<<<(NE + 255) / 256, 256>>>(ei);
    k_init<<<2048, 256>>>(out);
    k_gemm<<<(NN + 63) / 64, 256>>>(x, W);
    k_att<<<(NN + 7) / 8, 256>>>(att_src, att_dst);
    k_edge_w<<<(NE + 255) / 256, 256>>>();
    k_aggregate<<<(NE + 7) / 8, 256>>>(out);
    k_bnstats<<<1024, 256>>>(out);
    k_bnfinal<<<1, 128>>>(gamma, beta);
    k_norm<<<2048, 256>>>(out);
}